// round 16
// baseline (speedup 1.0000x reference)
#include <cuda_runtime.h>
#include <cuda_bf16.h>
#include <mma.h>
#include <math.h>
#include <stdint.h>

using namespace nvcuda;

#define BB   32
#define SS   200
#define SM1  199
#define MTOT (BB*SM1)   // 6368
#define MPAD 6400       // 50 * 128
#define MC   4

typedef unsigned long long ull;

// ---------------- device-global scratch ----------------
__device__ float d_gx[(size_t)MTOT*1024];
__device__ float d_hq[(size_t)MTOT*768];
__device__ float d_hc[(size_t)MTOT*768];
__device__ float d_hqa[(size_t)MTOT*256];
__device__ float d_hca[(size_t)MTOT*256];

// bf16 hi/lo split operands (pad rows stay zero)
__device__ __nv_bfloat16 g_qca_hi[(size_t)MPAD*1024];
__device__ __nv_bfloat16 g_qca_lo[(size_t)MPAD*1024];
__device__ __nv_bfloat16 g_wih_hi[1024*1024];
__device__ __nv_bfloat16 g_wih_lo[1024*1024];
__device__ __nv_bfloat16 g_hnx_hi[(size_t)MPAD*768];
__device__ __nv_bfloat16 g_hnx_lo[(size_t)MPAD*768];
__device__ __nv_bfloat16 g_hal_hi[(size_t)MPAD*256];
__device__ __nv_bfloat16 g_hal_lo[(size_t)MPAD*256];
__device__ __nv_bfloat16 g_wqn_hi[768*768];
__device__ __nv_bfloat16 g_wqn_lo[768*768];
__device__ __nv_bfloat16 g_wcn_hi[768*768];
__device__ __nv_bfloat16 g_wcn_lo[768*768];
__device__ __nv_bfloat16 g_wqa_hi[256*256];
__device__ __nv_bfloat16 g_wqa_lo[256*256];
__device__ __nv_bfloat16 g_wca_hi[256*256];
__device__ __nv_bfloat16 g_wca_lo[256*256];

__device__ __forceinline__ float sigmoidf_(float x) { return 1.f / (1.f + expf(-x)); }

__device__ __forceinline__ float fast_sig(float x) {
    x = fmaxf(fminf(x, 30.f), -30.f);
    return __fdividef(1.f, 1.f + __expf(-x));
}
__device__ __forceinline__ float fast_tanh(float x) {
    x = fmaxf(fminf(x, 15.f), -15.f);
    float t = __expf(2.f * x);
    return __fdividef(t - 1.f, t + 1.f);
}

__device__ __forceinline__ void wsplit(__nv_bfloat16* hi, __nv_bfloat16* lo, size_t i, float v) {
    __nv_bfloat16 h = __float2bfloat16_rn(v);
    hi[i] = h;
    lo[i] = __float2bfloat16_rn(v - __bfloat162float(h));
}

// f32x2 helpers
__device__ __forceinline__ void fma2(ull &acc, ull a, ull b) {
    asm("fma.rn.f32x2 %0, %1, %2, %0;" : "+l"(acc) : "l"(a), "l"(b));
}
__device__ __forceinline__ float2 upk(ull v) {
    float2 r; asm("mov.b64 {%0,%1}, %2;" : "=f"(r.x), "=f"(r.y) : "l"(v)); return r;
}
__device__ __forceinline__ uint32_t smem_u32(const void* p) {
    uint32_t a;
    asm("{ .reg .u64 t; cvta.to.shared.u64 t, %1; cvt.u32.u64 %0, t; }" : "=r"(a) : "l"(p));
    return a;
}
__device__ __forceinline__ void st_dsmem(uint32_t addr, float v) {
    asm volatile("st.shared::cluster.f32 [%0], %1;" :: "r"(addr), "f"(v) : "memory");
}
__device__ __forceinline__ uint32_t mapa_(uint32_t addr, uint32_t rank) {
    uint32_t r;
    asm("mapa.shared::cluster.u32 %0, %1, %2;" : "=r"(r) : "r"(addr), "r"(rank));
    return r;
}
__device__ __forceinline__ void cluster_sync_() {
    asm volatile("barrier.cluster.arrive.aligned;" ::: "memory");
    asm volatile("barrier.cluster.wait.aligned;" ::: "memory");
}
__device__ __forceinline__ void cluster_arrive_() {
    asm volatile("barrier.cluster.arrive.aligned;" ::: "memory");
}
__device__ __forceinline__ void cluster_wait_() {
    asm volatile("barrier.cluster.wait.aligned;" ::: "memory");
}
__device__ __forceinline__ void cp16(uint32_t dst, const void* src) {
    asm volatile("cp.async.cg.shared.global [%0], [%1], 16;" :: "r"(dst), "l"(src));
}

// ---------------- embeddings: qca (LSTM input) + hnx emb-half directly ----------------
__global__ void embed_kernel(const int* __restrict__ q, const int* __restrict__ c,
                             const int* __restrict__ r,
                             const float* __restrict__ que_emb,
                             const float* __restrict__ concept_emb) {
    int bs = blockIdx.x;
    int b = bs / SS, s = bs % SS;
    int e = threadIdx.x;
    int qi = q[bs];
    float eq = que_emb[(size_t)qi*256 + e];
    float sum = 0.f; int cnt = 0;
    #pragma unroll
    for (int j = 0; j < MC; j++) {
        int cj = c[bs*MC + j];
        if (cj >= 0) { sum += concept_emb[(size_t)cj*256 + e]; cnt++; }
    }
    float ec = sum / (float)max(cnt, 1);
    if (s < SM1) {
        float f1 = (float)r[bs];
        float f0 = 1.f - f1;
        size_t mb = ((size_t)b*SM1 + s) * 1024;
        wsplit(g_qca_hi, g_qca_lo, mb + e,       eq * f0);
        wsplit(g_qca_hi, g_qca_lo, mb + 256 + e, ec * f0);
        wsplit(g_qca_hi, g_qca_lo, mb + 512 + e, eq * f1);
        wsplit(g_qca_hi, g_qca_lo, mb + 768 + e, ec * f1);
    }
    if (s >= 1) {
        size_t mh = ((size_t)b*SM1 + (s-1)) * 768;
        wsplit(g_hnx_hi, g_hnx_lo, mh + e,       eq);
        wsplit(g_hnx_hi, g_hnx_lo, mh + 256 + e, ec);
    }
}

// ---------------- segmented f32 -> bf16 hi/lo split (all 4 head weights) ----------
__global__ void cvt_split4(const float* __restrict__ s0, __nv_bfloat16* __restrict__ h0p, __nv_bfloat16* __restrict__ l0p, int n0,
                           const float* __restrict__ s1, __nv_bfloat16* __restrict__ h1p, __nv_bfloat16* __restrict__ l1p, int n1,
                           const float* __restrict__ s2, __nv_bfloat16* __restrict__ h2p, __nv_bfloat16* __restrict__ l2p, int n2,
                           const float* __restrict__ s3, __nv_bfloat16* __restrict__ h3p, __nv_bfloat16* __restrict__ l3p, int n3) {
    int gi = (blockIdx.x * 256 + threadIdx.x) * 4;
    const float* s; __nv_bfloat16 *hi, *lo; int i;
    if (gi < n0)                { s = s0; hi = h0p; lo = l0p; i = gi; }
    else if (gi < n0+n1)        { s = s1; hi = h1p; lo = l1p; i = gi - n0; }
    else if (gi < n0+n1+n2)     { s = s2; hi = h2p; lo = l2p; i = gi - n0 - n1; }
    else if (gi < n0+n1+n2+n3)  { s = s3; hi = h3p; lo = l3p; i = gi - n0 - n1 - n2; }
    else return;
    float4 v = *reinterpret_cast<const float4*>(s + i);
    __nv_bfloat16 a0 = __float2bfloat16_rn(v.x), a1 = __float2bfloat16_rn(v.y);
    __nv_bfloat16 a2 = __float2bfloat16_rn(v.z), a3 = __float2bfloat16_rn(v.w);
    __nv_bfloat16 b0 = __float2bfloat16_rn(v.x - __bfloat162float(a0));
    __nv_bfloat16 b1 = __float2bfloat16_rn(v.y - __bfloat162float(a1));
    __nv_bfloat16 b2 = __float2bfloat16_rn(v.z - __bfloat162float(a2));
    __nv_bfloat16 b3 = __float2bfloat16_rn(v.w - __bfloat162float(a3));
    reinterpret_cast<__nv_bfloat162*>(hi + i)[0] = __halves2bfloat162(a0, a1);
    reinterpret_cast<__nv_bfloat162*>(hi + i)[1] = __halves2bfloat162(a2, a3);
    reinterpret_cast<__nv_bfloat162*>(lo + i)[0] = __halves2bfloat162(b0, b1);
    reinterpret_cast<__nv_bfloat162*>(lo + i)[1] = __halves2bfloat162(b2, b3);
}

__global__ void cvt_split(const float* __restrict__ s, __nv_bfloat16* __restrict__ hi,
                          __nv_bfloat16* __restrict__ lo, int n) {
    int i = (blockIdx.x * 256 + threadIdx.x) * 4;
    if (i >= n) return;
    float4 v = *reinterpret_cast<const float4*>(s + i);
    __nv_bfloat16 h0 = __float2bfloat16_rn(v.x), h1 = __float2bfloat16_rn(v.y);
    __nv_bfloat16 h2 = __float2bfloat16_rn(v.z), h3 = __float2bfloat16_rn(v.w);
    __nv_bfloat16 l0 = __float2bfloat16_rn(v.x - __bfloat162float(h0));
    __nv_bfloat16 l1 = __float2bfloat16_rn(v.y - __bfloat162float(h1));
    __nv_bfloat16 l2 = __float2bfloat16_rn(v.z - __bfloat162float(h2));
    __nv_bfloat16 l3 = __float2bfloat16_rn(v.w - __bfloat162float(h3));
    reinterpret_cast<__nv_bfloat162*>(hi + i)[0] = __halves2bfloat162(h0, h1);
    reinterpret_cast<__nv_bfloat162*>(hi + i)[1] = __halves2bfloat162(h2, h3);
    reinterpret_cast<__nv_bfloat162*>(lo + i)[0] = __halves2bfloat162(l0, l1);
    reinterpret_cast<__nv_bfloat162*>(lo + i)[1] = __halves2bfloat162(l2, l3);
}

// ---------------- shared GEMM tile body ----------------
__device__ __forceinline__ void gemm_tile_body(
    const __nv_bfloat16* Ahi, const __nv_bfloat16* Alo,
    const __nv_bfloat16* Bhi, const __nv_bfloat16* Blo,
    const float* bias, const float* bias2,
    float* C, int M, int N, int K, int relu, int m0, int n0, char* smem)
{
    __shared__ float sbias[128];
    int tid = threadIdx.x;
    int w = tid >> 5, lane = tid & 31;
    int wm = w >> 1, wn = w & 1;

    if (tid < 128) sbias[tid] = bias[n0 + tid] + (bias2 ? bias2[n0 + tid] : 0.f);

    wmma::fragment<wmma::accumulator, 16, 16, 16, float> acc[2][4];
    #pragma unroll
    for (int i = 0; i < 2; i++)
        #pragma unroll
        for (int j = 0; j < 4; j++) wmma::fill_fragment(acc[i][j], 0.f);

    const __nv_bfloat16* mats[4] = {Ahi, Alo, Bhi, Blo};
    const int r0s[4] = {m0, m0, n0, n0};
    uint32_t sb = smem_u32(smem);
    const uint32_t STG = 40960;
    int nk = K >> 5;

    {
        #pragma unroll
        for (int it = 0; it < 8; it++) {
            int o = tid + (it << 8);
            int mt = o >> 9, idx = o & 511;
            int row = idx >> 2, cc = idx & 3;
            cp16(sb + (uint32_t)(mt*10240 + row*80 + cc*16),
                 mats[mt] + (size_t)(r0s[mt] + row) * K + cc*8);
        }
        asm volatile("cp.async.commit_group;" ::: "memory");
    }

    for (int i = 0; i < nk; i++) {
        if (i + 1 < nk) {
            int k0 = (i + 1) << 5;
            uint32_t dstb = sb + (uint32_t)((i + 1) & 1) * STG;
            #pragma unroll
            for (int it = 0; it < 8; it++) {
                int o = tid + (it << 8);
                int mt = o >> 9, idx = o & 511;
                int row = idx >> 2, cc = idx & 3;
                cp16(dstb + (uint32_t)(mt*10240 + row*80 + cc*16),
                     mats[mt] + (size_t)(r0s[mt] + row) * K + k0 + cc*8);
            }
            asm volatile("cp.async.commit_group;" ::: "memory");
            asm volatile("cp.async.wait_group 1;" ::: "memory");
        } else {
            asm volatile("cp.async.wait_group 0;" ::: "memory");
        }
        __syncthreads();

        const __nv_bfloat16* cur =
            reinterpret_cast<const __nv_bfloat16*>(smem + (size_t)(i & 1) * STG);
        const __nv_bfloat16* tAh = cur;
        const __nv_bfloat16* tAl = cur + 5120;
        const __nv_bfloat16* tBh = cur + 10240;
        const __nv_bfloat16* tBl = cur + 15360;

        #pragma unroll
        for (int ks = 0; ks < 32; ks += 16) {
            wmma::fragment<wmma::matrix_a, 16, 16, 16, __nv_bfloat16, wmma::row_major> ah[2], al[2];
            #pragma unroll
            for (int i2 = 0; i2 < 2; i2++) {
                wmma::load_matrix_sync(ah[i2], tAh + (wm*32 + i2*16) * 40 + ks, 40);
                wmma::load_matrix_sync(al[i2], tAl + (wm*32 + i2*16) * 40 + ks, 40);
            }
            #pragma unroll
            for (int j = 0; j < 4; j++) {
                wmma::fragment<wmma::matrix_b, 16, 16, 16, __nv_bfloat16, wmma::col_major> bh, bl;
                wmma::load_matrix_sync(bh, tBh + (wn*64 + j*16) * 40 + ks, 40);
                wmma::load_matrix_sync(bl, tBl + (wn*64 + j*16) * 40 + ks, 40);
                #pragma unroll
                for (int i2 = 0; i2 < 2; i2++) {
                    wmma::mma_sync(acc[i2][j], ah[i2], bh, acc[i2][j]);
                    wmma::mma_sync(acc[i2][j], ah[i2], bl, acc[i2][j]);
                    wmma::mma_sync(acc[i2][j], al[i2], bh, acc[i2][j]);
                }
            }
        }
        __syncthreads();
    }

    float* stage = reinterpret_cast<float*>(smem) + w * 320;
    int r = lane >> 1, c0 = (lane & 1) * 8;
    #pragma unroll
    for (int i = 0; i < 2; i++) {
        #pragma unroll
        for (int j = 0; j < 4; j++) {
            wmma::store_matrix_sync(stage, acc[i][j], 20, wmma::mem_row_major);
            __syncwarp();
            int gm = m0 + wm*32 + i*16 + r;
            if (gm < M) {
                int nc = wn*64 + j*16 + c0;
                float4 v0, v1;
                v0.x = stage[r*20 + c0 + 0] + sbias[nc + 0];
                v0.y = stage[r*20 + c0 + 1] + sbias[nc + 1];
                v0.z = stage[r*20 + c0 + 2] + sbias[nc + 2];
                v0.w = stage[r*20 + c0 + 3] + sbias[nc + 3];
                v1.x = stage[r*20 + c0 + 4] + sbias[nc + 4];
                v1.y = stage[r*20 + c0 + 5] + sbias[nc + 5];
                v1.z = stage[r*20 + c0 + 6] + sbias[nc + 6];
                v1.w = stage[r*20 + c0 + 7] + sbias[nc + 7];
                if (relu) {
                    v0.x = fmaxf(v0.x, 0.f); v0.y = fmaxf(v0.y, 0.f);
                    v0.z = fmaxf(v0.z, 0.f); v0.w = fmaxf(v0.w, 0.f);
                    v1.x = fmaxf(v1.x, 0.f); v1.y = fmaxf(v1.y, 0.f);
                    v1.w = fmaxf(v1.w, 0.f); v1.z = fmaxf(v1.z, 0.f);
                }
                *reinterpret_cast<float4*>(&C[(size_t)gm * N + n0 + nc])     = v0;
                *reinterpret_cast<float4*>(&C[(size_t)gm * N + n0 + nc + 4]) = v1;
            }
            __syncwarp();
        }
    }
}

// ---------------- gx GEMM ----------------
#define GEMM_SMEM 81920
__global__ __launch_bounds__(256, 2) void mma_gemm(
    const __nv_bfloat16* __restrict__ Ahi, const __nv_bfloat16* __restrict__ Alo,
    const __nv_bfloat16* __restrict__ Bhi, const __nv_bfloat16* __restrict__ Blo,
    const float* __restrict__ bias, const float* __restrict__ bias2,
    float* __restrict__ C, int M, int N, int K, int relu)
{
    extern __shared__ __align__(16) char smem[];
    gemm_tile_body(Ahi, Alo, Bhi, Blo, bias, bias2, C, M, N, K, relu,
                   blockIdx.y * 128, blockIdx.x * 128, smem);
}

// ---------------- fused 4-head GEMM ----------------
__global__ __launch_bounds__(256, 2) void mma_gemm4(
    const __nv_bfloat16* Ahi0, const __nv_bfloat16* Alo0,
    const __nv_bfloat16* Bh0, const __nv_bfloat16* Bl0, const float* bi0, float* C0,
    const __nv_bfloat16* Bh1, const __nv_bfloat16* Bl1, const float* bi1, float* C1,
    const __nv_bfloat16* Ahi2, const __nv_bfloat16* Alo2,
    const __nv_bfloat16* Bh2, const __nv_bfloat16* Bl2, const float* bi2, float* C2,
    const __nv_bfloat16* Bh3, const __nv_bfloat16* Bl3, const float* bi3, float* C3)
{
    extern __shared__ __align__(16) char smem[];
    int bx = blockIdx.x;
    const __nv_bfloat16 *Ahi, *Alo, *Bhi, *Blo; const float* bias; float* C;
    int N, K, cb;
    if (bx < 6)       { Ahi=Ahi0; Alo=Alo0; Bhi=Bh0; Blo=Bl0; bias=bi0; C=C0; N=768; K=768; cb=bx; }
    else if (bx < 12) { Ahi=Ahi0; Alo=Alo0; Bhi=Bh1; Blo=Bl1; bias=bi1; C=C1; N=768; K=768; cb=bx-6; }
    else if (bx < 14) { Ahi=Ahi2; Alo=Alo2; Bhi=Bh2; Blo=Bl2; bias=bi2; C=C2; N=256; K=256; cb=bx-12; }
    else              { Ahi=Ahi2; Alo=Alo2; Bhi=Bh3; Blo=Bl3; bias=bi3; C=C3; N=256; K=256; cb=bx-14; }
    gemm_tile_body(Ahi, Alo, Bhi, Blo, bias, nullptr, C, MTOT, N, K, 1,
                   blockIdx.y * 128, cb * 128, smem);
}

// ---------------- cluster LSTM (best measured; writes hal + hnx h-part directly) ----
__global__ __cluster_dims__(8,1,1) __launch_bounds__(256, 1)
void lstm_kernel(const float* __restrict__ w_hh) {
    __shared__ __align__(16) float hbuf[2][2][288];

    int tid  = threadIdx.x;
    int rk   = blockIdx.x & 7;
    int cl   = blockIdx.x >> 3;
    int j    = tid >> 3;
    int kg   = tid & 7;
    int gj   = rk * 32 + j;

    ull w2[4][16];
    #pragma unroll
    for (int g = 0; g < 4; g++) {
        const ulonglong2* wp = reinterpret_cast<const ulonglong2*>(
            &w_hh[(size_t)(g*256 + gj) * 256 + kg*32]);
        #pragma unroll
        for (int i = 0; i < 8; i++) {
            ulonglong2 u = wp[i];
            w2[g][2*i]   = u.x;
            w2[g][2*i+1] = u.y;
        }
    }

    for (int i = tid; i < 2*2*288; i += 256) (&hbuf[0][0][0])[i] = 0.f;
    __syncthreads();
    cluster_sync_();

    uint32_t hb = smem_u32(&hbuf[0][0][0]);
    uint32_t rhb[8];
    #pragma unroll
    for (int rr = 0; rr < 8; rr++) rhb[rr] = mapa_(hb, (uint32_t)rr);

    const bool ispw = ((kg & 3) == 0);
    const int  pb   = kg >> 2;
    size_t gxb = ((size_t)(2*cl + pb) * SM1) * 1024 + gj;
    float gxc[4];
    if (ispw) {
        #pragma unroll
        for (int g = 0; g < 4; g++) gxc[g] = __ldcg(&d_gx[gxb + g*256]);
    }
    float cst = 0.f;

    for (int t = 0; t < SM1; t++) {
        int ph = t & 1;
        const ulonglong2* hp0 = reinterpret_cast<const ulonglong2*>(&hbuf[ph][0][kg*36]);
        const ulonglong2* hp1 = reinterpret_cast<const ulonglong2*>(&hbuf[ph][1][kg*36]);

        ull acc[4][2];
        #pragma unroll
        for (int g = 0; g < 4; g++) { acc[g][0] = 0ULL; acc[g][1] = 0ULL; }

        #pragma unroll
        for (int i = 0; i < 8; i++) {
            ulonglong2 u0 = hp0[i];
            ulonglong2 u1 = hp1[i];
            #pragma unroll
            for (int g = 0; g < 4; g++) {
                fma2(acc[g][0], w2[g][2*i],   u0.x);
                fma2(acc[g][0], w2[g][2*i+1], u0.y);
                fma2(acc[g][1], w2[g][2*i],   u1.x);
                fma2(acc[g][1], w2[g][2*i+1], u1.y);
            }
        }

        float s[8];
        #pragma unroll
        for (int g = 0; g < 4; g++) {
            float2 a0 = upk(acc[g][0]); s[g]     = a0.x + a0.y;
            float2 a1 = upk(acc[g][1]); s[4 + g] = a1.x + a1.y;
        }
        #pragma unroll
        for (int d = 4; d; d >>= 1) {
            #pragma unroll
            for (int v = 0; v < 8; v++)
                s[v] += __shfl_xor_sync(0xffffffffu, s[v], d, 8);
        }

        float h_mine = 0.f;
        if (ispw) {
            int base = pb * 4;
            float cn = fast_sig(s[base+1] + gxc[1]) * cst
                     + fast_sig(s[base+0] + gxc[0]) * fast_tanh(s[base+2] + gxc[2]);
            h_mine = fast_sig(s[base+3] + gxc[3]) * fast_tanh(cn);
            cst = cn;
            uint32_t off = (uint32_t)((((t+1)&1)*2 + pb)*288 + rk*36 + j) * 4u;
            #pragma unroll
            for (int rr = 0; rr < 8; rr++)
                st_dsmem(rhb[rr] + off, h_mine);
        }

        cluster_arrive_();

        if (ispw) {
            size_t m = (size_t)(2*cl + pb) * SM1 + t;
            size_t r0 = m * 256 + gj;
            __nv_bfloat16 hh = __float2bfloat16_rn(h_mine);
            __nv_bfloat16 hl = __float2bfloat16_rn(h_mine - __bfloat162float(hh));
            g_hal_hi[r0] = hh;
            g_hal_lo[r0] = hl;
            size_t rh = m * 768 + 512 + gj;   // hnext h-part, written directly
            g_hnx_hi[rh] = hh;
            g_hnx_lo[rh] = hl;
            if (t + 1 < SM1) {
                size_t o = (size_t)(t + 1) * 1024;
                #pragma unroll
                for (int g = 0; g < 4; g++) gxc[g] = __ldcg(&d_gx[gxb + o + g*256]);
            }
        }

        cluster_wait_();
    }
}

// ---------------- gathered output heads ----------------
__device__ __forceinline__ float warp_sum(float v) {
    #pragma unroll
    for (int o = 16; o; o >>= 1) v += __shfl_xor_sync(0xffffffffu, v, o);
    return v;
}

__global__ __launch_bounds__(256) void gather_kernel(
    const int* __restrict__ qshft, const int* __restrict__ cshft,
    const float* __restrict__ qn_ow, const float* __restrict__ qn_ob,
    const float* __restrict__ cn_ow, const float* __restrict__ cn_ob,
    const float* __restrict__ qa_ow, const float* __restrict__ qa_ob,
    const float* __restrict__ ca_ow, const float* __restrict__ ca_ob,
    float* __restrict__ out)
{
    int m = blockIdx.x * 8 + (threadIdx.x >> 5);
    int lane = threadIdx.x & 31;

    float acc = 0.f;
    for (int k = lane; k < 768; k += 32)
        acc += d_hq[(size_t)m*768 + k] * qn_ow[k];
    float yqn = sigmoidf_(warp_sum(acc) + qn_ob[0]);

    float ysum = 0.f; int cnt = 0;
    #pragma unroll
    for (int j = 0; j < MC; j++) {
        int cc = cshft[m*MC + j];
        if (cc >= 0) {
            float a = 0.f;
            for (int k = lane; k < 768; k += 32)
                a += d_hc[(size_t)m*768 + k] * cn_ow[(size_t)cc*768 + k];
            ysum += sigmoidf_(warp_sum(a) + cn_ob[cc]);
            cnt++;
        }
    }
    float ycn = ysum / (float)max(cnt, 1);

    int qi = qshft[m];
    float a2 = 0.f;
    for (int k = lane; k < 256; k += 32)
        a2 += d_hqa[(size_t)m*256 + k] * qa_ow[(size_t)qi*256 + k];
    float yqa = sigmoidf_(warp_sum(a2) + qa_ob[qi]);

    float ysum2 = 0.f; int cnt2 = 0;
    #pragma unroll
    for (int j = 0; j < MC; j++) {
        int cc = cshft[m*MC + j];
        if (cc >= 0) {
            float a = 0.f;
            for (int k = lane; k < 256; k += 32)
                a += d_hca[(size_t)m*256 + k] * ca_ow[(size_t)cc*256 + k];
            ysum2 += sigmoidf_(warp_sum(a) + ca_ob[cc]);
            cnt2++;
        }
    }
    float yca = ysum2 / (float)max(cnt2, 1);

    if (lane == 0) {
        out[m]            = yqn;
        out[MTOT + m]     = ycn;
        out[2*MTOT + m]   = yqa;
        out[3*MTOT + m]   = yca;
    }
}

// ---------------- launch ----------------
extern "C" void kernel_launch(void* const* d_in, const int* in_sizes, int n_in,
                              void* d_out, int out_size) {
    const int*   q           = (const int*)d_in[0];
    const int*   c           = (const int*)d_in[1];
    const int*   r           = (const int*)d_in[2];
    const int*   qshft       = (const int*)d_in[3];
    const int*   cshft       = (const int*)d_in[4];
    const float* que_emb     = (const float*)d_in[5];
    const float* concept_emb = (const float*)d_in[6];
    const float* w_ih        = (const float*)d_in[7];
    const float* w_hh        = (const float*)d_in[8];
    const float* b_ih        = (const float*)d_in[9];
    const float* b_hh        = (const float*)d_in[10];
    const float* qn_lw = (const float*)d_in[11];
    const float* qn_lb = (const float*)d_in[12];
    const float* qn_ow = (const float*)d_in[13];
    const float* qn_ob = (const float*)d_in[14];
    const float* cn_lw = (const float*)d_in[15];
    const float* cn_lb = (const float*)d_in[16];
    const float* cn_ow = (const float*)d_in[17];
    const float* cn_ob = (const float*)d_in[18];
    const float* qa_lw = (const float*)d_in[19];
    const float* qa_lb = (const float*)d_in[20];
    const float* qa_ow = (const float*)d_in[21];
    const float* qa_ob = (const float*)d_in[22];
    const float* ca_lw = (const float*)d_in[23];
    const float* ca_lb = (const float*)d_in[24];
    const float* ca_ow = (const float*)d_in[25];
    const float* ca_ob = (const float*)d_in[26];
    float* out = (float*)d_out;

    static bool init_done = false;
    static cudaStream_t s2;
    static cudaEvent_t evF1, evJ1, evF2, evJ2;
    if (!init_done) {
        cudaFuncSetAttribute(mma_gemm,  cudaFuncAttributeMaxDynamicSharedMemorySize, GEMM_SMEM);
        cudaFuncSetAttribute(mma_gemm4, cudaFuncAttributeMaxDynamicSharedMemorySize, GEMM_SMEM);
        cudaStreamCreateWithFlags(&s2, cudaStreamNonBlocking);
        cudaEventCreateWithFlags(&evF1, cudaEventDisableTiming);
        cudaEventCreateWithFlags(&evJ1, cudaEventDisableTiming);
        cudaEventCreateWithFlags(&evF2, cudaEventDisableTiming);
        cudaEventCreateWithFlags(&evJ2, cudaEventDisableTiming);
        init_done = true;
    }

    float* p_gx;  cudaGetSymbolAddress((void**)&p_gx,  d_gx);
    float* p_hq;  cudaGetSymbolAddress((void**)&p_hq,  d_hq);
    float* p_hc;  cudaGetSymbolAddress((void**)&p_hc,  d_hc);
    float* p_hqa; cudaGetSymbolAddress((void**)&p_hqa, d_hqa);
    float* p_hca; cudaGetSymbolAddress((void**)&p_hca, d_hca);
    __nv_bfloat16 *p_qca_hi, *p_qca_lo, *p_wih_hi, *p_wih_lo;
    __nv_bfloat16 *p_hnx_hi, *p_hnx_lo, *p_hal_hi, *p_hal_lo;
    __nv_bfloat16 *p_wqn_hi, *p_wqn_lo, *p_wcn_hi, *p_wcn_lo;
    __nv_bfloat16 *p_wqa_hi, *p_wqa_lo, *p_wca_hi, *p_wca_lo;
    cudaGetSymbolAddress((void**)&p_qca_hi, g_qca_hi);
    cudaGetSymbolAddress((void**)&p_qca_lo, g_qca_lo);
    cudaGetSymbolAddress((void**)&p_wih_hi, g_wih_hi);
    cudaGetSymbolAddress((void**)&p_wih_lo, g_wih_lo);
    cudaGetSymbolAddress((void**)&p_hnx_hi, g_hnx_hi);
    cudaGetSymbolAddress((void**)&p_hnx_lo, g_hnx_lo);
    cudaGetSymbolAddress((void**)&p_hal_hi, g_hal_hi);
    cudaGetSymbolAddress((void**)&p_hal_lo, g_hal_lo);
    cudaGetSymbolAddress((void**)&p_wqn_hi, g_wqn_hi);
    cudaGetSymbolAddress((void**)&p_wqn_lo, g_wqn_lo);
    cudaGetSymbolAddress((void**)&p_wcn_hi, g_wcn_hi);
    cudaGetSymbolAddress((void**)&p_wcn_lo, g_wcn_lo);
    cudaGetSymbolAddress((void**)&p_wqa_hi, g_wqa_hi);
    cudaGetSymbolAddress((void**)&p_wqa_lo, g_wqa_lo);
    cudaGetSymbolAddress((void**)&p_wca_hi, g_wca_hi);
    cudaGetSymbolAddress((void**)&p_wca_lo, g_wca_lo);

    // fork 1: w_ih split (side) || embeddings (main)
    cudaEventRecord(evF1, 0);
    cudaStreamWaitEvent(s2, evF1, 0);
    embed_kernel<<<BB*SS, 256>>>(q, c, r, que_emb, concept_emb);
    cvt_split<<<(1024*1024/4 + 255)/256, 256, 0, s2>>>(w_ih, p_wih_hi, p_wih_lo, 1024*1024);
    cudaEventRecord(evJ1, s2);
    cudaStreamWaitEvent(0, evJ1, 0);

    // gx = qca @ w_ih^T + b_ih + b_hh
    { dim3 g(8, 50); mma_gemm<<<g, 256, GEMM_SMEM>>>(p_qca_hi, p_qca_lo, p_wih_hi, p_wih_lo,
                                                     b_ih, b_hh, p_gx, MTOT, 1024, 1024, 0); }

    // fork 2: 4 head-weight splits (side) || LSTM (main)
    cudaEventRecord(evF2, 0);
    cudaStreamWaitEvent(s2, evF2, 0);
    lstm_kernel<<<128, 256>>>(w_hh);
    {
        int n0 = 768*768, n1 = 768*768, n2 = 256*256, n3 = 256*256;
        int tot4 = (n0 + n1 + n2 + n3) / 4;
        cvt_split4<<<(tot4 + 255)/256, 256, 0, s2>>>(
            qn_lw, p_wqn_hi, p_wqn_lo, n0,
            cn_lw, p_wcn_hi, p_wcn_lo, n1,
            qa_lw, p_wqa_hi, p_wqa_lo, n2,
            ca_lw, p_wca_hi, p_wca_lo, n3);
    }
    cudaEventRecord(evJ2, s2);
    cudaStreamWaitEvent(0, evJ2, 0);

    // all four head GEMMs in one launch (hnext now fully written by embed + lstm)
    {
        dim3 g(16, 50);
        mma_gemm4<<<g, 256, GEMM_SMEM>>>(
            p_hnx_hi, p_hnx_lo,
            p_wqn_hi, p_wqn_lo, qn_lb, p_hq,
            p_wcn_hi, p_wcn_lo, cn_lb, p_hc,
            p_hal_hi, p_hal_lo,
            p_wqa_hi, p_wqa_lo, qa_lb, p_hqa,
            p_wca_hi, p_wca_lo, ca_lb, p_hca);
    }
    // gathered heads
    gather_kernel<<<MTOT/8, 256>>>(qshft, cshft, qn_ow, qn_ob, cn_ow, cn_ob,
                                   qa_ow, qa_ob, ca_ow, ca_ob, out);
    (void)in_sizes; (void)n_in; (void)out_size;
}

// round 17
// speedup vs baseline: 1.0183x; 1.0183x over previous
#include <cuda_runtime.h>
#include <cuda_bf16.h>
#include <mma.h>
#include <math.h>
#include <stdint.h>

using namespace nvcuda;

#define BB   32
#define SS   200
#define SM1  199
#define MTOT (BB*SM1)   // 6368
#define MPAD 6400       // 50 * 128
#define MC   4

typedef unsigned long long ull;

// ---------------- device-global scratch ----------------
__device__ float d_gx[(size_t)MTOT*1024];
__device__ float d_hq[(size_t)MTOT*768];
__device__ float d_hc[(size_t)MTOT*768];
__device__ float d_hqa[(size_t)MTOT*256];
__device__ float d_hca[(size_t)MTOT*256];

// bf16 hi/lo split operands (pad rows stay zero)
__device__ __nv_bfloat16 g_qca_hi[(size_t)MPAD*1024];
__device__ __nv_bfloat16 g_qca_lo[(size_t)MPAD*1024];
__device__ __nv_bfloat16 g_wih_hi[1024*1024];
__device__ __nv_bfloat16 g_wih_lo[1024*1024];
__device__ __nv_bfloat16 g_hnx_hi[(size_t)MPAD*768];
__device__ __nv_bfloat16 g_hnx_lo[(size_t)MPAD*768];
__device__ __nv_bfloat16 g_hal_hi[(size_t)MPAD*256];
__device__ __nv_bfloat16 g_hal_lo[(size_t)MPAD*256];
__device__ __nv_bfloat16 g_wqn_hi[768*768];
__device__ __nv_bfloat16 g_wqn_lo[768*768];
__device__ __nv_bfloat16 g_wcn_hi[768*768];
__device__ __nv_bfloat16 g_wcn_lo[768*768];
__device__ __nv_bfloat16 g_wqa_hi[256*256];
__device__ __nv_bfloat16 g_wqa_lo[256*256];
__device__ __nv_bfloat16 g_wca_hi[256*256];
__device__ __nv_bfloat16 g_wca_lo[256*256];

__device__ __forceinline__ float sigmoidf_(float x) { return 1.f / (1.f + expf(-x)); }

__device__ __forceinline__ float fast_sig(float x) {
    x = fmaxf(fminf(x, 30.f), -30.f);
    return __fdividef(1.f, 1.f + __expf(-x));
}
__device__ __forceinline__ float fast_tanh(float x) {
    x = fmaxf(fminf(x, 15.f), -15.f);
    float t = __expf(2.f * x);
    return __fdividef(t - 1.f, t + 1.f);
}

__device__ __forceinline__ void wsplit(__nv_bfloat16* hi, __nv_bfloat16* lo, size_t i, float v) {
    __nv_bfloat16 h = __float2bfloat16_rn(v);
    hi[i] = h;
    lo[i] = __float2bfloat16_rn(v - __bfloat162float(h));
}

// f32x2 helpers
__device__ __forceinline__ void fma2(ull &acc, ull a, ull b) {
    asm("fma.rn.f32x2 %0, %1, %2, %0;" : "+l"(acc) : "l"(a), "l"(b));
}
__device__ __forceinline__ float2 upk(ull v) {
    float2 r; asm("mov.b64 {%0,%1}, %2;" : "=f"(r.x), "=f"(r.y) : "l"(v)); return r;
}
__device__ __forceinline__ uint32_t smem_u32(const void* p) {
    uint32_t a;
    asm("{ .reg .u64 t; cvta.to.shared.u64 t, %1; cvt.u32.u64 %0, t; }" : "=r"(a) : "l"(p));
    return a;
}
__device__ __forceinline__ void st_dsmem(uint32_t addr, float v) {
    asm volatile("st.shared::cluster.f32 [%0], %1;" :: "r"(addr), "f"(v) : "memory");
}
__device__ __forceinline__ uint32_t mapa_(uint32_t addr, uint32_t rank) {
    uint32_t r;
    asm("mapa.shared::cluster.u32 %0, %1, %2;" : "=r"(r) : "r"(addr), "r"(rank));
    return r;
}
__device__ __forceinline__ void cluster_sync_() {
    asm volatile("barrier.cluster.arrive.aligned;" ::: "memory");
    asm volatile("barrier.cluster.wait.aligned;" ::: "memory");
}
__device__ __forceinline__ void cluster_arrive_() {
    asm volatile("barrier.cluster.arrive.aligned;" ::: "memory");
}
__device__ __forceinline__ void cluster_wait_() {
    asm volatile("barrier.cluster.wait.aligned;" ::: "memory");
}
__device__ __forceinline__ void cp16(uint32_t dst, const void* src) {
    asm volatile("cp.async.cg.shared.global [%0], [%1], 16;" :: "r"(dst), "l"(src));
}

// ---------------- embeddings: qca (LSTM input) + hnx emb-half directly ----------------
__global__ void embed_kernel(const int* __restrict__ q, const int* __restrict__ c,
                             const int* __restrict__ r,
                             const float* __restrict__ que_emb,
                             const float* __restrict__ concept_emb) {
    int bs = blockIdx.x;
    int b = bs / SS, s = bs % SS;
    int e = threadIdx.x;
    int qi = q[bs];
    float eq = que_emb[(size_t)qi*256 + e];
    float sum = 0.f; int cnt = 0;
    #pragma unroll
    for (int j = 0; j < MC; j++) {
        int cj = c[bs*MC + j];
        if (cj >= 0) { sum += concept_emb[(size_t)cj*256 + e]; cnt++; }
    }
    float ec = sum / (float)max(cnt, 1);
    if (s < SM1) {
        float f1 = (float)r[bs];
        float f0 = 1.f - f1;
        size_t mb = ((size_t)b*SM1 + s) * 1024;
        wsplit(g_qca_hi, g_qca_lo, mb + e,       eq * f0);
        wsplit(g_qca_hi, g_qca_lo, mb + 256 + e, ec * f0);
        wsplit(g_qca_hi, g_qca_lo, mb + 512 + e, eq * f1);
        wsplit(g_qca_hi, g_qca_lo, mb + 768 + e, ec * f1);
    }
    if (s >= 1) {
        size_t mh = ((size_t)b*SM1 + (s-1)) * 768;
        wsplit(g_hnx_hi, g_hnx_lo, mh + e,       eq);
        wsplit(g_hnx_hi, g_hnx_lo, mh + 256 + e, ec);
    }
}

// ---------------- hnext: fill h-part (cols 512..767) from hal hi/lo ----------------
__global__ void hnext_kernel() {
    int m = blockIdx.x;
    int e = threadIdx.x;
    size_t hi = (size_t)m*256 + e;
    float hv = __bfloat162float(g_hal_hi[hi]) + __bfloat162float(g_hal_lo[hi]);
    wsplit(g_hnx_hi, g_hnx_lo, (size_t)m*768 + 512 + e, hv);
}

// ---------------- segmented f32 -> bf16 hi/lo split (all 4 head weights) ----------
__global__ void cvt_split4(const float* __restrict__ s0, __nv_bfloat16* __restrict__ h0p, __nv_bfloat16* __restrict__ l0p, int n0,
                           const float* __restrict__ s1, __nv_bfloat16* __restrict__ h1p, __nv_bfloat16* __restrict__ l1p, int n1,
                           const float* __restrict__ s2, __nv_bfloat16* __restrict__ h2p, __nv_bfloat16* __restrict__ l2p, int n2,
                           const float* __restrict__ s3, __nv_bfloat16* __restrict__ h3p, __nv_bfloat16* __restrict__ l3p, int n3) {
    int gi = (blockIdx.x * 256 + threadIdx.x) * 4;
    const float* s; __nv_bfloat16 *hi, *lo; int i;
    if (gi < n0)                { s = s0; hi = h0p; lo = l0p; i = gi; }
    else if (gi < n0+n1)        { s = s1; hi = h1p; lo = l1p; i = gi - n0; }
    else if (gi < n0+n1+n2)     { s = s2; hi = h2p; lo = l2p; i = gi - n0 - n1; }
    else if (gi < n0+n1+n2+n3)  { s = s3; hi = h3p; lo = l3p; i = gi - n0 - n1 - n2; }
    else return;
    float4 v = *reinterpret_cast<const float4*>(s + i);
    __nv_bfloat16 a0 = __float2bfloat16_rn(v.x), a1 = __float2bfloat16_rn(v.y);
    __nv_bfloat16 a2 = __float2bfloat16_rn(v.z), a3 = __float2bfloat16_rn(v.w);
    __nv_bfloat16 b0 = __float2bfloat16_rn(v.x - __bfloat162float(a0));
    __nv_bfloat16 b1 = __float2bfloat16_rn(v.y - __bfloat162float(a1));
    __nv_bfloat16 b2 = __float2bfloat16_rn(v.z - __bfloat162float(a2));
    __nv_bfloat16 b3 = __float2bfloat16_rn(v.w - __bfloat162float(a3));
    reinterpret_cast<__nv_bfloat162*>(hi + i)[0] = __halves2bfloat162(a0, a1);
    reinterpret_cast<__nv_bfloat162*>(hi + i)[1] = __halves2bfloat162(a2, a3);
    reinterpret_cast<__nv_bfloat162*>(lo + i)[0] = __halves2bfloat162(b0, b1);
    reinterpret_cast<__nv_bfloat162*>(lo + i)[1] = __halves2bfloat162(b2, b3);
}

__global__ void cvt_split(const float* __restrict__ s, __nv_bfloat16* __restrict__ hi,
                          __nv_bfloat16* __restrict__ lo, int n) {
    int i = (blockIdx.x * 256 + threadIdx.x) * 4;
    if (i >= n) return;
    float4 v = *reinterpret_cast<const float4*>(s + i);
    __nv_bfloat16 h0 = __float2bfloat16_rn(v.x), h1 = __float2bfloat16_rn(v.y);
    __nv_bfloat16 h2 = __float2bfloat16_rn(v.z), h3 = __float2bfloat16_rn(v.w);
    __nv_bfloat16 l0 = __float2bfloat16_rn(v.x - __bfloat162float(h0));
    __nv_bfloat16 l1 = __float2bfloat16_rn(v.y - __bfloat162float(h1));
    __nv_bfloat16 l2 = __float2bfloat16_rn(v.z - __bfloat162float(h2));
    __nv_bfloat16 l3 = __float2bfloat16_rn(v.w - __bfloat162float(h3));
    reinterpret_cast<__nv_bfloat162*>(hi + i)[0] = __halves2bfloat162(h0, h1);
    reinterpret_cast<__nv_bfloat162*>(hi + i)[1] = __halves2bfloat162(h2, h3);
    reinterpret_cast<__nv_bfloat162*>(lo + i)[0] = __halves2bfloat162(l0, l1);
    reinterpret_cast<__nv_bfloat162*>(lo + i)[1] = __halves2bfloat162(l2, l3);
}

// ---------------- shared GEMM tile body ----------------
__device__ __forceinline__ void gemm_tile_body(
    const __nv_bfloat16* Ahi, const __nv_bfloat16* Alo,
    const __nv_bfloat16* Bhi, const __nv_bfloat16* Blo,
    const float* bias, const float* bias2,
    float* C, int M, int N, int K, int relu, int m0, int n0, char* smem)
{
    __shared__ float sbias[128];
    int tid = threadIdx.x;
    int w = tid >> 5, lane = tid & 31;
    int wm = w >> 1, wn = w & 1;

    if (tid < 128) sbias[tid] = bias[n0 + tid] + (bias2 ? bias2[n0 + tid] : 0.f);

    wmma::fragment<wmma::accumulator, 16, 16, 16, float> acc[2][4];
    #pragma unroll
    for (int i = 0; i < 2; i++)
        #pragma unroll
        for (int j = 0; j < 4; j++) wmma::fill_fragment(acc[i][j], 0.f);

    const __nv_bfloat16* mats[4] = {Ahi, Alo, Bhi, Blo};
    const int r0s[4] = {m0, m0, n0, n0};
    uint32_t sb = smem_u32(smem);
    const uint32_t STG = 40960;
    int nk = K >> 5;

    {
        #pragma unroll
        for (int it = 0; it < 8; it++) {
            int o = tid + (it << 8);
            int mt = o >> 9, idx = o & 511;
            int row = idx >> 2, cc = idx & 3;
            cp16(sb + (uint32_t)(mt*10240 + row*80 + cc*16),
                 mats[mt] + (size_t)(r0s[mt] + row) * K + cc*8);
        }
        asm volatile("cp.async.commit_group;" ::: "memory");
    }

    for (int i = 0; i < nk; i++) {
        if (i + 1 < nk) {
            int k0 = (i + 1) << 5;
            uint32_t dstb = sb + (uint32_t)((i + 1) & 1) * STG;
            #pragma unroll
            for (int it = 0; it < 8; it++) {
                int o = tid + (it << 8);
                int mt = o >> 9, idx = o & 511;
                int row = idx >> 2, cc = idx & 3;
                cp16(dstb + (uint32_t)(mt*10240 + row*80 + cc*16),
                     mats[mt] + (size_t)(r0s[mt] + row) * K + k0 + cc*8);
            }
            asm volatile("cp.async.commit_group;" ::: "memory");
            asm volatile("cp.async.wait_group 1;" ::: "memory");
        } else {
            asm volatile("cp.async.wait_group 0;" ::: "memory");
        }
        __syncthreads();

        const __nv_bfloat16* cur =
            reinterpret_cast<const __nv_bfloat16*>(smem + (size_t)(i & 1) * STG);
        const __nv_bfloat16* tAh = cur;
        const __nv_bfloat16* tAl = cur + 5120;
        const __nv_bfloat16* tBh = cur + 10240;
        const __nv_bfloat16* tBl = cur + 15360;

        #pragma unroll
        for (int ks = 0; ks < 32; ks += 16) {
            wmma::fragment<wmma::matrix_a, 16, 16, 16, __nv_bfloat16, wmma::row_major> ah[2], al[2];
            #pragma unroll
            for (int i2 = 0; i2 < 2; i2++) {
                wmma::load_matrix_sync(ah[i2], tAh + (wm*32 + i2*16) * 40 + ks, 40);
                wmma::load_matrix_sync(al[i2], tAl + (wm*32 + i2*16) * 40 + ks, 40);
            }
            #pragma unroll
            for (int j = 0; j < 4; j++) {
                wmma::fragment<wmma::matrix_b, 16, 16, 16, __nv_bfloat16, wmma::col_major> bh, bl;
                wmma::load_matrix_sync(bh, tBh + (wn*64 + j*16) * 40 + ks, 40);
                wmma::load_matrix_sync(bl, tBl + (wn*64 + j*16) * 40 + ks, 40);
                #pragma unroll
                for (int i2 = 0; i2 < 2; i2++) {
                    wmma::mma_sync(acc[i2][j], ah[i2], bh, acc[i2][j]);
                    wmma::mma_sync(acc[i2][j], ah[i2], bl, acc[i2][j]);
                    wmma::mma_sync(acc[i2][j], al[i2], bh, acc[i2][j]);
                }
            }
        }
        __syncthreads();
    }

    float* stage = reinterpret_cast<float*>(smem) + w * 320;
    int r = lane >> 1, c0 = (lane & 1) * 8;
    #pragma unroll
    for (int i = 0; i < 2; i++) {
        #pragma unroll
        for (int j = 0; j < 4; j++) {
            wmma::store_matrix_sync(stage, acc[i][j], 20, wmma::mem_row_major);
            __syncwarp();
            int gm = m0 + wm*32 + i*16 + r;
            if (gm < M) {
                int nc = wn*64 + j*16 + c0;
                float4 v0, v1;
                v0.x = stage[r*20 + c0 + 0] + sbias[nc + 0];
                v0.y = stage[r*20 + c0 + 1] + sbias[nc + 1];
                v0.z = stage[r*20 + c0 + 2] + sbias[nc + 2];
                v0.w = stage[r*20 + c0 + 3] + sbias[nc + 3];
                v1.x = stage[r*20 + c0 + 4] + sbias[nc + 4];
                v1.y = stage[r*20 + c0 + 5] + sbias[nc + 5];
                v1.z = stage[r*20 + c0 + 6] + sbias[nc + 6];
                v1.w = stage[r*20 + c0 + 7] + sbias[nc + 7];
                if (relu) {
                    v0.x = fmaxf(v0.x, 0.f); v0.y = fmaxf(v0.y, 0.f);
                    v0.z = fmaxf(v0.z, 0.f); v0.w = fmaxf(v0.w, 0.f);
                    v1.x = fmaxf(v1.x, 0.f); v1.y = fmaxf(v1.y, 0.f);
                    v1.z = fmaxf(v1.z, 0.f); v1.w = fmaxf(v1.w, 0.f);
                }
                *reinterpret_cast<float4*>(&C[(size_t)gm * N + n0 + nc])     = v0;
                *reinterpret_cast<float4*>(&C[(size_t)gm * N + n0 + nc + 4]) = v1;
            }
            __syncwarp();
        }
    }
}

// ---------------- gx GEMM ----------------
#define GEMM_SMEM 81920
__global__ __launch_bounds__(256, 2) void mma_gemm(
    const __nv_bfloat16* __restrict__ Ahi, const __nv_bfloat16* __restrict__ Alo,
    const __nv_bfloat16* __restrict__ Bhi, const __nv_bfloat16* __restrict__ Blo,
    const float* __restrict__ bias, const float* __restrict__ bias2,
    float* __restrict__ C, int M, int N, int K, int relu)
{
    extern __shared__ __align__(16) char smem[];
    gemm_tile_body(Ahi, Alo, Bhi, Blo, bias, bias2, C, M, N, K, relu,
                   blockIdx.y * 128, blockIdx.x * 128, smem);
}

// ---------------- fused 4-head GEMM ----------------
__global__ __launch_bounds__(256, 2) void mma_gemm4(
    const __nv_bfloat16* Ahi0, const __nv_bfloat16* Alo0,
    const __nv_bfloat16* Bh0, const __nv_bfloat16* Bl0, const float* bi0, float* C0,
    const __nv_bfloat16* Bh1, const __nv_bfloat16* Bl1, const float* bi1, float* C1,
    const __nv_bfloat16* Ahi2, const __nv_bfloat16* Alo2,
    const __nv_bfloat16* Bh2, const __nv_bfloat16* Bl2, const float* bi2, float* C2,
    const __nv_bfloat16* Bh3, const __nv_bfloat16* Bl3, const float* bi3, float* C3)
{
    extern __shared__ __align__(16) char smem[];
    int bx = blockIdx.x;
    const __nv_bfloat16 *Ahi, *Alo, *Bhi, *Blo; const float* bias; float* C;
    int N, K, cb;
    if (bx < 6)       { Ahi=Ahi0; Alo=Alo0; Bhi=Bh0; Blo=Bl0; bias=bi0; C=C0; N=768; K=768; cb=bx; }
    else if (bx < 12) { Ahi=Ahi0; Alo=Alo0; Bhi=Bh1; Blo=Bl1; bias=bi1; C=C1; N=768; K=768; cb=bx-6; }
    else if (bx < 14) { Ahi=Ahi2; Alo=Alo2; Bhi=Bh2; Blo=Bl2; bias=bi2; C=C2; N=256; K=256; cb=bx-12; }
    else              { Ahi=Ahi2; Alo=Alo2; Bhi=Bh3; Blo=Bl3; bias=bi3; C=C3; N=256; K=256; cb=bx-14; }
    gemm_tile_body(Ahi, Alo, Bhi, Blo, bias, nullptr, C, MTOT, N, K, 1,
                   blockIdx.y * 128, cb * 128, smem);
}

// ---------------- cluster LSTM (best measured: barrier.cluster split arrive/wait) ----
__global__ __cluster_dims__(8,1,1) __launch_bounds__(256, 1)
void lstm_kernel(const float* __restrict__ w_hh) {
    __shared__ __align__(16) float hbuf[2][2][288];

    int tid  = threadIdx.x;
    int rk   = blockIdx.x & 7;
    int cl   = blockIdx.x >> 3;
    int j    = tid >> 3;
    int kg   = tid & 7;
    int gj   = rk * 32 + j;

    ull w2[4][16];
    #pragma unroll
    for (int g = 0; g < 4; g++) {
        const ulonglong2* wp = reinterpret_cast<const ulonglong2*>(
            &w_hh[(size_t)(g*256 + gj) * 256 + kg*32]);
        #pragma unroll
        for (int i = 0; i < 8; i++) {
            ulonglong2 u = wp[i];
            w2[g][2*i]   = u.x;
            w2[g][2*i+1] = u.y;
        }
    }

    for (int i = tid; i < 2*2*288; i += 256) (&hbuf[0][0][0])[i] = 0.f;
    __syncthreads();
    cluster_sync_();

    uint32_t hb = smem_u32(&hbuf[0][0][0]);
    uint32_t rhb[8];
    #pragma unroll
    for (int rr = 0; rr < 8; rr++) rhb[rr] = mapa_(hb, (uint32_t)rr);

    const bool ispw = ((kg & 3) == 0);
    const int  pb   = kg >> 2;
    size_t gxb = ((size_t)(2*cl + pb) * SM1) * 1024 + gj;
    float gxc[4];
    if (ispw) {
        #pragma unroll
        for (int g = 0; g < 4; g++) gxc[g] = __ldcg(&d_gx[gxb + g*256]);
    }
    float cst = 0.f;

    for (int t = 0; t < SM1; t++) {
        int ph = t & 1;
        const ulonglong2* hp0 = reinterpret_cast<const ulonglong2*>(&hbuf[ph][0][kg*36]);
        const ulonglong2* hp1 = reinterpret_cast<const ulonglong2*>(&hbuf[ph][1][kg*36]);

        ull acc[4][2];
        #pragma unroll
        for (int g = 0; g < 4; g++) { acc[g][0] = 0ULL; acc[g][1] = 0ULL; }

        #pragma unroll
        for (int i = 0; i < 8; i++) {
            ulonglong2 u0 = hp0[i];
            ulonglong2 u1 = hp1[i];
            #pragma unroll
            for (int g = 0; g < 4; g++) {
                fma2(acc[g][0], w2[g][2*i],   u0.x);
                fma2(acc[g][0], w2[g][2*i+1], u0.y);
                fma2(acc[g][1], w2[g][2*i],   u1.x);
                fma2(acc[g][1], w2[g][2*i+1], u1.y);
            }
        }

        float s[8];
        #pragma unroll
        for (int g = 0; g < 4; g++) {
            float2 a0 = upk(acc[g][0]); s[g]     = a0.x + a0.y;
            float2 a1 = upk(acc[g][1]); s[4 + g] = a1.x + a1.y;
        }
        #pragma unroll
        for (int d = 4; d; d >>= 1) {
            #pragma unroll
            for (int v = 0; v < 8; v++)
                s[v] += __shfl_xor_sync(0xffffffffu, s[v], d, 8);
        }

        float h_mine = 0.f;
        if (ispw) {
            int base = pb * 4;
            float cn = fast_sig(s[base+1] + gxc[1]) * cst
                     + fast_sig(s[base+0] + gxc[0]) * fast_tanh(s[base+2] + gxc[2]);
            h_mine = fast_sig(s[base+3] + gxc[3]) * fast_tanh(cn);
            cst = cn;
            uint32_t off = (uint32_t)((((t+1)&1)*2 + pb)*288 + rk*36 + j) * 4u;
            #pragma unroll
            for (int rr = 0; rr < 8; rr++)
                st_dsmem(rhb[rr] + off, h_mine);
        }

        cluster_arrive_();

        if (ispw) {
            size_t r0 = ((size_t)(2*cl + pb) * SM1 + t) * 256 + gj;
            __nv_bfloat16 hh = __float2bfloat16_rn(h_mine);
            g_hal_hi[r0] = hh;
            g_hal_lo[r0] = __float2bfloat16_rn(h_mine - __bfloat162float(hh));
            if (t + 1 < SM1) {
                size_t o = (size_t)(t + 1) * 1024;
                #pragma unroll
                for (int g = 0; g < 4; g++) gxc[g] = __ldcg(&d_gx[gxb + o + g*256]);
            }
        }

        cluster_wait_();
    }
}

// ---------------- gathered output heads ----------------
__device__ __forceinline__ float warp_sum(float v) {
    #pragma unroll
    for (int o = 16; o; o >>= 1) v += __shfl_xor_sync(0xffffffffu, v, o);
    return v;
}

__global__ __launch_bounds__(256) void gather_kernel(
    const int* __restrict__ qshft, const int* __restrict__ cshft,
    const float* __restrict__ qn_ow, const float* __restrict__ qn_ob,
    const float* __restrict__ cn_ow, const float* __restrict__ cn_ob,
    const float* __restrict__ qa_ow, const float* __restrict__ qa_ob,
    const float* __restrict__ ca_ow, const float* __restrict__ ca_ob,
    float* __restrict__ out)
{
    int m = blockIdx.x * 8 + (threadIdx.x >> 5);
    int lane = threadIdx.x & 31;

    float acc = 0.f;
    for (int k = lane; k < 768; k += 32)
        acc += d_hq[(size_t)m*768 + k] * qn_ow[k];
    float yqn = sigmoidf_(warp_sum(acc) + qn_ob[0]);

    float ysum = 0.f; int cnt = 0;
    #pragma unroll
    for (int j = 0; j < MC; j++) {
        int cc = cshft[m*MC + j];
        if (cc >= 0) {
            float a = 0.f;
            for (int k = lane; k < 768; k += 32)
                a += d_hc[(size_t)m*768 + k] * cn_ow[(size_t)cc*768 + k];
            ysum += sigmoidf_(warp_sum(a) + cn_ob[cc]);
            cnt++;
        }
    }
    float ycn = ysum / (float)max(cnt, 1);

    int qi = qshft[m];
    float a2 = 0.f;
    for (int k = lane; k < 256; k += 32)
        a2 += d_hqa[(size_t)m*256 + k] * qa_ow[(size_t)qi*256 + k];
    float yqa = sigmoidf_(warp_sum(a2) + qa_ob[qi]);

    float ysum2 = 0.f; int cnt2 = 0;
    #pragma unroll
    for (int j = 0; j < MC; j++) {
        int cc = cshft[m*MC + j];
        if (cc >= 0) {
            float a = 0.f;
            for (int k = lane; k < 256; k += 32)
                a += d_hca[(size_t)m*256 + k] * ca_ow[(size_t)cc*256 + k];
            ysum2 += sigmoidf_(warp_sum(a) + ca_ob[cc]);
            cnt2++;
        }
    }
    float yca = ysum2 / (float)max(cnt2, 1);

    if (lane == 0) {
        out[m]            = yqn;
        out[MTOT + m]     = ycn;
        out[2*MTOT + m]   = yqa;
        out[3*MTOT + m]   = yca;
    }
}

// ---------------- launch ----------------
extern "C" void kernel_launch(void* const* d_in, const int* in_sizes, int n_in,
                              void* d_out, int out_size) {
    const int*   q           = (const int*)d_in[0];
    const int*   c           = (const int*)d_in[1];
    const int*   r           = (const int*)d_in[2];
    const int*   qshft       = (const int*)d_in[3];
    const int*   cshft       = (const int*)d_in[4];
    const float* que_emb     = (const float*)d_in[5];
    const float* concept_emb = (const float*)d_in[6];
    const float* w_ih        = (const float*)d_in[7];
    const float* w_hh        = (const float*)d_in[8];
    const float* b_ih        = (const float*)d_in[9];
    const float* b_hh        = (const float*)d_in[10];
    const float* qn_lw = (const float*)d_in[11];
    const float* qn_lb = (const float*)d_in[12];
    const float* qn_ow = (const float*)d_in[13];
    const float* qn_ob = (const float*)d_in[14];
    const float* cn_lw = (const float*)d_in[15];
    const float* cn_lb = (const float*)d_in[16];
    const float* cn_ow = (const float*)d_in[17];
    const float* cn_ob = (const float*)d_in[18];
    const float* qa_lw = (const float*)d_in[19];
    const float* qa_lb = (const float*)d_in[20];
    const float* qa_ow = (const float*)d_in[21];
    const float* qa_ob = (const float*)d_in[22];
    const float* ca_lw = (const float*)d_in[23];
    const float* ca_lb = (const float*)d_in[24];
    const float* ca_ow = (const float*)d_in[25];
    const float* ca_ob = (const float*)d_in[26];
    float* out = (float*)d_out;

    static bool init_done = false;
    static cudaStream_t s2;
    static cudaEvent_t evF1, evJ1, evF2, evJ2;
    if (!init_done) {
        cudaFuncSetAttribute(mma_gemm,  cudaFuncAttributeMaxDynamicSharedMemorySize, GEMM_SMEM);
        cudaFuncSetAttribute(mma_gemm4, cudaFuncAttributeMaxDynamicSharedMemorySize, GEMM_SMEM);
        cudaStreamCreateWithFlags(&s2, cudaStreamNonBlocking);
        cudaEventCreateWithFlags(&evF1, cudaEventDisableTiming);
        cudaEventCreateWithFlags(&evJ1, cudaEventDisableTiming);
        cudaEventCreateWithFlags(&evF2, cudaEventDisableTiming);
        cudaEventCreateWithFlags(&evJ2, cudaEventDisableTiming);
        init_done = true;
    }

    float* p_gx;  cudaGetSymbolAddress((void**)&p_gx,  d_gx);
    float* p_hq;  cudaGetSymbolAddress((void**)&p_hq,  d_hq);
    float* p_hc;  cudaGetSymbolAddress((void**)&p_hc,  d_hc);
    float* p_hqa; cudaGetSymbolAddress((void**)&p_hqa, d_hqa);
    float* p_hca; cudaGetSymbolAddress((void**)&p_hca, d_hca);
    __nv_bfloat16 *p_qca_hi, *p_qca_lo, *p_wih_hi, *p_wih_lo;
    __nv_bfloat16 *p_hnx_hi, *p_hnx_lo, *p_hal_hi, *p_hal_lo;
    __nv_bfloat16 *p_wqn_hi, *p_wqn_lo, *p_wcn_hi, *p_wcn_lo;
    __nv_bfloat16 *p_wqa_hi, *p_wqa_lo, *p_wca_hi, *p_wca_lo;
    cudaGetSymbolAddress((void**)&p_qca_hi, g_qca_hi);
    cudaGetSymbolAddress((void**)&p_qca_lo, g_qca_lo);
    cudaGetSymbolAddress((void**)&p_wih_hi, g_wih_hi);
    cudaGetSymbolAddress((void**)&p_wih_lo, g_wih_lo);
    cudaGetSymbolAddress((void**)&p_hnx_hi, g_hnx_hi);
    cudaGetSymbolAddress((void**)&p_hnx_lo, g_hnx_lo);
    cudaGetSymbolAddress((void**)&p_hal_hi, g_hal_hi);
    cudaGetSymbolAddress((void**)&p_hal_lo, g_hal_lo);
    cudaGetSymbolAddress((void**)&p_wqn_hi, g_wqn_hi);
    cudaGetSymbolAddress((void**)&p_wqn_lo, g_wqn_lo);
    cudaGetSymbolAddress((void**)&p_wcn_hi, g_wcn_hi);
    cudaGetSymbolAddress((void**)&p_wcn_lo, g_wcn_lo);
    cudaGetSymbolAddress((void**)&p_wqa_hi, g_wqa_hi);
    cudaGetSymbolAddress((void**)&p_wqa_lo, g_wqa_lo);
    cudaGetSymbolAddress((void**)&p_wca_hi, g_wca_hi);
    cudaGetSymbolAddress((void**)&p_wca_lo, g_wca_lo);

    // fork 1: w_ih split (side) || embeddings (main)
    cudaEventRecord(evF1, 0);
    cudaStreamWaitEvent(s2, evF1, 0);
    embed_kernel<<<BB*SS, 256>>>(q, c, r, que_emb, concept_emb);
    cvt_split<<<(1024*1024/4 + 255)/256, 256, 0, s2>>>(w_ih, p_wih_hi, p_wih_lo, 1024*1024);
    cudaEventRecord(evJ1, s2);
    cudaStreamWaitEvent(0, evJ1, 0);

    // gx = qca @ w_ih^T + b_ih + b_hh
    { dim3 g(8, 50); mma_gemm<<<g, 256, GEMM_SMEM>>>(p_qca_hi, p_qca_lo, p_wih_hi, p_wih_lo,
                                                     b_ih, b_hh, p_gx, MTOT, 1024, 1024, 0); }

    // fork 2: 4 head-weight splits (side) || LSTM (main)
    cudaEventRecord(evF2, 0);
    cudaStreamWaitEvent(s2, evF2, 0);
    lstm_kernel<<<128, 256>>>(w_hh);
    {
        int n0 = 768*768, n1 = 768*768, n2 = 256*256, n3 = 256*256;
        int tot4 = (n0 + n1 + n2 + n3) / 4;
        cvt_split4<<<(tot4 + 255)/256, 256, 0, s2>>>(
            qn_lw, p_wqn_hi, p_wqn_lo, n0,
            cn_lw, p_wcn_hi, p_wcn_lo, n1,
            qa_lw, p_wqa_hi, p_wqa_lo, n2,
            ca_lw, p_wca_hi, p_wca_lo, n3);
    }
    cudaEventRecord(evJ2, s2);
    cudaStreamWaitEvent(0, evJ2, 0);

    // hnext h-part (after LSTM)
    hnext_kernel<<<MTOT, 256>>>();
    // all four head GEMMs in one launch
    {
        dim3 g(16, 50);
        mma_gemm4<<<g, 256, GEMM_SMEM>>>(
            p_hnx_hi, p_hnx_lo,
            p_wqn_hi, p_wqn_lo, qn_lb, p_hq,
            p_wcn_hi, p_wcn_lo, cn_lb, p_hc,
            p_hal_hi, p_hal_lo,
            p_wqa_hi, p_wqa_lo, qa_lb, p_hqa,
            p_wca_hi, p_wca_lo, ca_lb, p_hca);
    }
    // gathered heads
    gather_kernel<<<MTOT/8, 256>>>(qshft, cshft, qn_ow, qn_ob, cn_ow, cn_ob,
                                   qa_ow, qa_ob, ca_ow, ca_ob, out);
    (void)in_sizes; (void)n_in; (void)out_size;
}